// round 5
// baseline (speedup 1.0000x reference)
#include <cuda_runtime.h>

// out[b, p, d] = x[b, p] * W[p, d] + bias[p, d]
// B=64, P=2000, D=512 (fp32). HBM-write-bound: 262MB out (~6.65TB/s achieved).
//
// R4 post-mortem: persistent grid-stride REGRESSED (45.4us) — HW CTA scheduler
// beats static assignment; grid-stride loop de-pipelines the store stream.
// Reverted to the R3 shape (scheduler-managed blocks, one W/b load per block,
// unrolled batch loop, .cs streaming stores), with B_CHUNK 8->4 to halve the
// wave-quantization tail (16000 blocks = 13.5 waves). Extra W/b re-reads stay
// in L2 (8MB resident), never touching DRAM.

#define B_DIM 64
#define P_DIM 2000
#define D_DIM 512
#define D4 (D_DIM / 4)              // 128
#define PD4 (P_DIM * D4)            // 256000
#define B_CHUNK 4                   // batches per thread
#define N_CHUNKS (B_DIM / B_CHUNK)  // 16

__global__ __launch_bounds__(256) void feature_expander_kernel(
    const float* __restrict__ x,      // [B, P]
    const float4* __restrict__ W,     // [P, D/4]
    const float4* __restrict__ bias,  // [P, D/4]
    float4* __restrict__ out)         // [B, P, D/4]
{
    int idx = blockIdx.x * blockDim.x + threadIdx.x;   // < PD4 always (1000*256)
    int p = idx >> 7;                                  // idx / 128
    int b0 = blockIdx.y * B_CHUNK;

    float4 w = __ldg(&W[idx]);
    float4 bv = __ldg(&bias[idx]);

    const float* xp = x + b0 * P_DIM + p;
    float4* op = out + (size_t)b0 * PD4 + idx;

    #pragma unroll
    for (int i = 0; i < B_CHUNK; i++) {
        float xv = __ldg(xp + i * P_DIM);
        float4 o;
        o.x = fmaf(xv, w.x, bv.x);
        o.y = fmaf(xv, w.y, bv.y);
        o.z = fmaf(xv, w.z, bv.z);
        o.w = fmaf(xv, w.w, bv.w);
        __stcs(op + (size_t)i * PD4, o);   // streaming store
    }
}

extern "C" void kernel_launch(void* const* d_in, const int* in_sizes, int n_in,
                              void* d_out, int out_size) {
    const float*  x  = (const float*)d_in[0];
    const float4* W  = (const float4*)d_in[1];
    const float4* bb = (const float4*)d_in[2];
    float4* out = (float4*)d_out;

    dim3 grid(PD4 / 256, N_CHUNKS);   // 1000 x 16
    feature_expander_kernel<<<grid, 256>>>(x, W, bb, out);
}

// round 6
// speedup vs baseline: 1.4889x; 1.4889x over previous
#include <cuda_runtime.h>

// out[b, p, d] = x[b, p] * W[p, d] + bias[p, d]
// B=64, P=2000, D=512 (fp32). HBM-write-bound: 262MB out (~6.55TB/s steady).
//
// Converged shape (R3 = 40.0us): thread = one (p,d4) float4 column x 8 batch
// rows; W/b loaded once per thread (L2-resident re-reads), .cs streaming
// stores. B_CHUNK sweep: 16->41.0, 8->40.0, 4->60.1 (LSU-bound) — 8 is the
// load/store-mix sweet spot. Persistent grid regressed (R4).
// This round: identical per-thread work, CTA 256->128 threads (grid 2000x8)
// for finer scheduling granularity / smaller drain quantum.

#define B_DIM 64
#define P_DIM 2000
#define D_DIM 512
#define D4 (D_DIM / 4)              // 128
#define PD4 (P_DIM * D4)            // 256000
#define B_CHUNK 8                   // batches per thread
#define N_CHUNKS (B_DIM / B_CHUNK)  // 8
#define TPB 128

__global__ __launch_bounds__(TPB) void feature_expander_kernel(
    const float* __restrict__ x,      // [B, P]
    const float4* __restrict__ W,     // [P, D/4]
    const float4* __restrict__ bias,  // [P, D/4]
    float4* __restrict__ out)         // [B, P, D/4]
{
    int idx = blockIdx.x * TPB + threadIdx.x;   // < PD4 always (2000*128)
    int p = idx >> 7;                           // idx / 128
    int b0 = blockIdx.y * B_CHUNK;

    float4 w = __ldg(&W[idx]);
    float4 bv = __ldg(&bias[idx]);

    const float* xp = x + b0 * P_DIM + p;
    float4* op = out + (size_t)b0 * PD4 + idx;

    #pragma unroll
    for (int i = 0; i < B_CHUNK; i++) {
        float xv = __ldg(xp + i * P_DIM);
        float4 o;
        o.x = fmaf(xv, w.x, bv.x);
        o.y = fmaf(xv, w.y, bv.y);
        o.z = fmaf(xv, w.z, bv.z);
        o.w = fmaf(xv, w.w, bv.w);
        __stcs(op + (size_t)i * PD4, o);   // streaming store
    }
}

extern "C" void kernel_launch(void* const* d_in, const int* in_sizes, int n_in,
                              void* d_out, int out_size) {
    const float*  x  = (const float*)d_in[0];
    const float4* W  = (const float4*)d_in[1];
    const float4* bb = (const float4*)d_in[2];
    float4* out = (float4*)d_out;

    dim3 grid(PD4 / TPB, N_CHUNKS);   // 2000 x 8
    feature_expander_kernel<<<grid, TPB>>>(x, W, bb, out);
}